// round 11
// baseline (speedup 1.0000x reference)
#include <cuda_runtime.h>
#include <cuda_bf16.h>
#include <mma.h>

using namespace nvcuda;

#define N_NODES 20000
#define N_PAD   20096
#define E_EDGES 640000
#define E_TOT   (E_EDGES + N_NODES)
#define IN_F    256
#define HEADS   8
#define HF      64
#define OUTF    32
#define NEG_SLOPE 0.2f
#define MAXDEG  128

// ------------------- scratch -------------------
__device__ __nv_bfloat16  g_h1b[(size_t)N_PAD * HEADS * HF];
__device__ float          g_h1m[(size_t)N_PAD * HF];
__device__ __nv_bfloat16  g_h2b[(size_t)N_PAD * HEADS * OUTF];
__device__ float g_as1[N_PAD * HEADS];
__device__ float g_ad1[N_PAD * HEADS];
__device__ float g_as2[N_PAD * HEADS];
__device__ float g_ad2[N_PAD * HEADS];
__device__ float g_w[(size_t)N_NODES * MAXDEG * HEADS];
__device__ int   g_cnt[N_NODES];
__device__ int   g_csr[(size_t)N_NODES * MAXDEG];
__device__ int   g_pos[E_TOT];

// ------------------- padded-bucket CSR build -------------------
__global__ void scatter_kernel(const int* __restrict__ src, const int* __restrict__ dst,
                               int* __restrict__ cnt, int* __restrict__ csr,
                               int* __restrict__ pos) {
    int i = blockIdx.x * blockDim.x + threadIdx.x;
    if (i >= E_TOT) return;
    int s, d;
    if (i < E_EDGES) { s = src[i]; d = dst[i]; }
    else             { s = d = i - E_EDGES; }
    int p = atomicAdd(&cnt[d], 1);
    int slot = (p < MAXDEG) ? d * MAXDEG + p : d * MAXDEG;
    csr[slot] = s;
    pos[i] = slot;
}

// ------------------- edge weights (padded slot order) -------------------
__global__ void weight_kernel(const int* __restrict__ src, const int* __restrict__ dst,
                              const int* __restrict__ pos,
                              const float* __restrict__ asrc, const float* __restrict__ adst,
                              float* __restrict__ w) {
    int i = blockIdx.x * blockDim.x + threadIdx.x;
    if (i >= E_TOT) return;
    int s, d;
    if (i < E_EDGES) { s = src[i]; d = dst[i]; }
    else             { s = d = i - E_EDGES; }
    int p = pos[i];
    float4 a0 = __ldg((const float4*)&asrc[s * HEADS]);
    float4 a1 = __ldg((const float4*)&asrc[s * HEADS + 4]);
    float4 d0 = __ldg((const float4*)&adst[d * HEADS]);
    float4 d1 = __ldg((const float4*)&adst[d * HEADS + 4]);
    float e[8] = {a0.x + d0.x, a0.y + d0.y, a0.z + d0.z, a0.w + d0.w,
                  a1.x + d1.x, a1.y + d1.y, a1.z + d1.z, a1.w + d1.w};
    float r[8];
    #pragma unroll
    for (int h = 0; h < 8; h++) {
        float v = e[h];
        v = (v >= 0.f) ? v : NEG_SLOPE * v;
        r[h] = __expf(v);
    }
    float* wp = w + (size_t)p * HEADS;
    *(float4*)wp       = make_float4(r[0], r[1], r[2], r[3]);
    *(float4*)(wp + 4) = make_float4(r[4], r[5], r[6], r[7]);
}

// ------------------- TF32 GEMM + fused logits/bf16 epilogue -------------------
template<int GUARD_A, int CH>
__global__ __launch_bounds__(256, 2)
void gemm_fused_kernel(const float* __restrict__ A, const float* __restrict__ B,
                       __nv_bfloat16* __restrict__ hb,
                       const float* __restrict__ att_src, const float* __restrict__ att_dst,
                       float* __restrict__ asrc, float* __restrict__ adst,
                       int M, int Nn, int K) {
    __shared__ float As[2][128][36];
    __shared__ float Bs[2][32][68];

    const int bm = blockIdx.y * 128;
    const int bn = blockIdx.x * 64;
    const int t = threadIdx.x;
    const int wid = t >> 5;
    const int lane = t & 31;
    const int wm = (wid & 3) * 32;
    const int wn = (wid >> 2) * 32;

    const int ar0 = (t * 4) >> 5;
    const int ac  = (t * 4) & 31;
    const int br0 = (t * 4) >> 6;
    const int bc  = (t * 4) & 63;

    wmma::fragment<wmma::accumulator, 16, 16, 8, float> c[2][2];
    #pragma unroll
    for (int i = 0; i < 2; i++)
        #pragma unroll
        for (int j = 0; j < 2; j++)
            wmma::fill_fragment(c[i][j], 0.0f);

    const int nk = K / 32;

    float4 aR[4], bR[2];
    #pragma unroll
    for (int i = 0; i < 4; i++) {
        int r = ar0 + i * 32;
        if (!GUARD_A || (bm + r) < M)
            aR[i] = *(const float4*)(A + (size_t)(bm + r) * K + ac);
        else
            aR[i] = make_float4(0.f, 0.f, 0.f, 0.f);
    }
    #pragma unroll
    for (int i = 0; i < 2; i++)
        bR[i] = *(const float4*)(B + (size_t)(br0 + i * 16) * Nn + bn + bc);

    #pragma unroll
    for (int i = 0; i < 4; i++) {
        float4 v = aR[i];
        v.x = wmma::__float_to_tf32(v.x); v.y = wmma::__float_to_tf32(v.y);
        v.z = wmma::__float_to_tf32(v.z); v.w = wmma::__float_to_tf32(v.w);
        *(float4*)&As[0][ar0 + i * 32][ac] = v;
    }
    #pragma unroll
    for (int i = 0; i < 2; i++) {
        float4 v = bR[i];
        v.x = wmma::__float_to_tf32(v.x); v.y = wmma::__float_to_tf32(v.y);
        v.z = wmma::__float_to_tf32(v.z); v.w = wmma::__float_to_tf32(v.w);
        *(float4*)&Bs[0][br0 + i * 16][bc] = v;
    }
    __syncthreads();

    for (int kt = 0; kt < nk; kt++) {
        const int cur = kt & 1;
        const int nxt = cur ^ 1;

        if (kt + 1 < nk) {
            int k0 = (kt + 1) * 32;
            #pragma unroll
            for (int i = 0; i < 4; i++) {
                int r = ar0 + i * 32;
                if (!GUARD_A || (bm + r) < M)
                    aR[i] = *(const float4*)(A + (size_t)(bm + r) * K + k0 + ac);
                else
                    aR[i] = make_float4(0.f, 0.f, 0.f, 0.f);
            }
            #pragma unroll
            for (int i = 0; i < 2; i++)
                bR[i] = *(const float4*)(B + (size_t)(k0 + br0 + i * 16) * Nn + bn + bc);
        }

        #pragma unroll
        for (int kk = 0; kk < 4; kk++) {
            wmma::fragment<wmma::matrix_a, 16, 16, 8, wmma::precision::tf32, wmma::row_major> a[2];
            wmma::fragment<wmma::matrix_b, 16, 16, 8, wmma::precision::tf32, wmma::row_major> b[2];
            #pragma unroll
            for (int i = 0; i < 2; i++)
                wmma::load_matrix_sync(a[i], &As[cur][wm + i * 16][kk * 8], 36);
            #pragma unroll
            for (int j = 0; j < 2; j++)
                wmma::load_matrix_sync(b[j], &Bs[cur][kk * 8][wn + j * 16], 68);
            #pragma unroll
            for (int i = 0; i < 2; i++)
                #pragma unroll
                for (int j = 0; j < 2; j++)
                    wmma::mma_sync(c[i][j], a[i], b[j], c[i][j]);
        }

        if (kt + 1 < nk) {
            #pragma unroll
            for (int i = 0; i < 4; i++) {
                float4 v = aR[i];
                v.x = wmma::__float_to_tf32(v.x); v.y = wmma::__float_to_tf32(v.y);
                v.z = wmma::__float_to_tf32(v.z); v.w = wmma::__float_to_tf32(v.w);
                *(float4*)&As[nxt][ar0 + i * 32][ac] = v;
            }
            #pragma unroll
            for (int i = 0; i < 2; i++) {
                float4 v = bR[i];
                v.x = wmma::__float_to_tf32(v.x); v.y = wmma::__float_to_tf32(v.y);
                v.z = wmma::__float_to_tf32(v.z); v.w = wmma::__float_to_tf32(v.w);
                *(float4*)&Bs[nxt][br0 + i * 16][bc] = v;
            }
        }
        __syncthreads();
    }

    float (*Cs)[68] = reinterpret_cast<float(*)[68]>(&As[0][0][0]);
    #pragma unroll
    for (int i = 0; i < 2; i++)
        #pragma unroll
        for (int j = 0; j < 2; j++)
            wmma::store_matrix_sync(&Cs[wm + i * 16][wn + j * 16], c[i][j], 68,
                                    wmma::mem_row_major);
    __syncthreads();

    const float a_s0 = __ldg(att_src + bn + lane * 2);
    const float a_s1 = __ldg(att_src + bn + lane * 2 + 1);
    const float a_d0 = __ldg(att_dst + bn + lane * 2);
    const float a_d1 = __ldg(att_dst + bn + lane * 2 + 1);

    #pragma unroll
    for (int rr = 0; rr < 16; rr++) {
        int r = wid * 16 + rr;
        float2 v = *(const float2*)&Cs[r][lane * 2];
        ((__nv_bfloat162*)(hb + (size_t)(bm + r) * Nn + bn))[lane] =
            __floats2bfloat162_rn(v.x, v.y);
        float s1 = v.x * a_s0 + v.y * a_s1;
        float s2 = v.x * a_d0 + v.y * a_d1;
        if (CH == 64) {
            #pragma unroll
            for (int o = 16; o > 0; o >>= 1) {
                s1 += __shfl_xor_sync(0xffffffffu, s1, o);
                s2 += __shfl_xor_sync(0xffffffffu, s2, o);
            }
            if (lane == 0) {
                int head = bn >> 6;
                asrc[(bm + r) * HEADS + head] = s1;
                adst[(bm + r) * HEADS + head] = s2;
            }
        } else {
            #pragma unroll
            for (int o = 8; o > 0; o >>= 1) {
                s1 += __shfl_xor_sync(0xffffffffu, s1, o);
                s2 += __shfl_xor_sync(0xffffffffu, s2, o);
            }
            if ((lane & 15) == 0) {
                int head = (bn >> 5) + (lane >> 4);
                asrc[(bm + r) * HEADS + head] = s1;
                adst[(bm + r) * HEADS + head] = s2;
            }
        }
    }
}

// ------------------- GAT aggregation: full-head warps, precomputed weights -------
// Each warp covers ALL 8 heads of one edge: head = lane>>2, CV = C/4 channels
// per lane. 8 warps = 8 edge chunks. w precomputed in slot order (no exp in
// the hot loop). Packed fma.rn.f32x2 accumulate, bf16->f32 via shift/mask.
template <int C, bool RELU>
__global__ __launch_bounds__(256)
void aggregate_kernel(const __nv_bfloat16* __restrict__ h, const float* __restrict__ w,
                      const int* __restrict__ cnt, const int* __restrict__ csr,
                      const float* __restrict__ bias, float* __restrict__ out) {
    constexpr int NQ = 8;
    constexpr int CV = C / 4;           // 16 (C=64) / 8 (C=32)
    constexpr int NACC = CV / 2;        // 8 / 4
    const int node = blockIdx.x;
    const int wid = threadIdx.x >> 5;
    const int lane = threadIdx.x & 31;
    const int q = wid;
    const int head = lane >> 2;
    const int cbase = (lane & 3) * CV;

    const int len = min(cnt[node], MAXDEG);
    const int chunk = (len + NQ - 1) / NQ;
    const int lo = node * MAXDEG + min(len, q * chunk);
    const int hi = node * MAXDEG + min(len, q * chunk + chunk);

    const unsigned rowBytes = (unsigned)(C * HEADS * 2);   // 1024 / 512
    const unsigned laneOff  = (unsigned)(head * C + cbase) * 2u;
    const char* hbase = (const char*)h;

    float den = 0.f;
    unsigned long long acc2[NACC];
    #pragma unroll
    for (int v = 0; v < NACC; v++) acc2[v] = 0ULL;

    for (int j = lo; j < hi; j++) {
        int s = __ldg(&csr[j]);
        float wj = __ldg(&w[j * HEADS + head]);
        den += wj;
        unsigned long long wj2;
        asm("mov.b64 %0, {%1, %1};" : "=l"(wj2) : "f"(wj));
        unsigned off = (unsigned)s * rowBytes + laneOff;
        uint4 r0 = __ldg((const uint4*)(hbase + off));
        unsigned raws[NACC];
        raws[0] = r0.x; raws[1] = r0.y; raws[2] = r0.z; raws[3] = r0.w;
        if (CV == 16) {
            uint4 r1 = __ldg((const uint4*)(hbase + off + 16));
            raws[4] = r1.x; raws[5] = r1.y; raws[6] = r1.z; raws[7] = r1.w;
        }
        #pragma unroll
        for (int k = 0; k < NACC; k++) {
            unsigned lo32 = raws[k] << 16;
            unsigned hi32 = raws[k] & 0xffff0000u;
            unsigned long long hv;
            asm("mov.b64 %0, {%1, %2};" : "=l"(hv) : "r"(lo32), "r"(hi32));
            asm("fma.rn.f32x2 %0, %1, %2, %0;" : "+l"(acc2[k]) : "l"(hv), "l"(wj2));
        }
    }

    __shared__ float sacc[NQ][HEADS][C];
    __shared__ float sden[NQ][HEADS];
    #pragma unroll
    for (int k = 0; k < NACC; k++) {
        float a0, a1;
        asm("mov.b64 {%0, %1}, %2;" : "=f"(a0), "=f"(a1) : "l"(acc2[k]));
        sacc[q][head][cbase + 2 * k]     = a0;
        sacc[q][head][cbase + 2 * k + 1] = a1;
    }
    if ((lane & 3) == 0) sden[q][head] = den;
    __syncthreads();

    if (threadIdx.x < C) {
        int cc = threadIdx.x;
        float sum = 0.f;
        #pragma unroll
        for (int hh = 0; hh < HEADS; hh++) {
            float a = 0.f, d = 0.f;
            #pragma unroll
            for (int qq = 0; qq < NQ; qq++) {
                a += sacc[qq][hh][cc];
                d += sden[qq][hh];
            }
            sum += a / d;
        }
        sum = sum * (1.0f / HEADS) + bias[cc];
        if (RELU) sum = fmaxf(sum, 0.f);
        out[(size_t)node * C + cc] = sum;
    }
}

// ------------------- launch -------------------
extern "C" void kernel_launch(void* const* d_in, const int* in_sizes, int n_in,
                              void* d_out, int out_size) {
    const float* x        = (const float*)d_in[0];
    const int*   ei       = (const int*)  d_in[1];
    const float* W1       = (const float*)d_in[2];
    const float* att_src1 = (const float*)d_in[3];
    const float* att_dst1 = (const float*)d_in[4];
    const float* b1       = (const float*)d_in[5];
    const float* W2       = (const float*)d_in[6];
    const float* att_src2 = (const float*)d_in[7];
    const float* att_dst2 = (const float*)d_in[8];
    const float* b2       = (const float*)d_in[9];
    float* out = (float*)d_out;

    const int* src = ei;
    const int* dst = ei + E_EDGES;

    float *h1m, *as1, *ad1, *as2, *ad2, *wbuf;
    __nv_bfloat16 *h1b, *h2b;
    int *cnt, *csr, *pos;
    cudaGetSymbolAddress((void**)&h1b,  g_h1b);
    cudaGetSymbolAddress((void**)&h1m,  g_h1m);
    cudaGetSymbolAddress((void**)&h2b,  g_h2b);
    cudaGetSymbolAddress((void**)&as1,  g_as1);
    cudaGetSymbolAddress((void**)&ad1,  g_ad1);
    cudaGetSymbolAddress((void**)&as2,  g_as2);
    cudaGetSymbolAddress((void**)&ad2,  g_ad2);
    cudaGetSymbolAddress((void**)&wbuf, g_w);
    cudaGetSymbolAddress((void**)&cnt,  g_cnt);
    cudaGetSymbolAddress((void**)&csr,  g_csr);
    cudaGetSymbolAddress((void**)&pos,  g_pos);

    cudaStream_t st = 0;
    const int threads = 256;
    const int eblocks = (E_TOT + threads - 1) / threads;

    cudaMemsetAsync(cnt, 0, N_NODES * sizeof(int), st);
    scatter_kernel<<<eblocks, threads, 0, st>>>(src, dst, cnt, csr, pos);

    // Layer 1
    {
        dim3 grid(HEADS * HF / 64, (N_NODES + 127) / 128);
        gemm_fused_kernel<1, HF><<<grid, 256, 0, st>>>(x, W1, h1b, att_src1, att_dst1,
                                                       as1, ad1, N_NODES, HEADS * HF, IN_F);
        weight_kernel<<<eblocks, threads, 0, st>>>(src, dst, pos, as1, ad1, wbuf);
        aggregate_kernel<HF, true><<<N_NODES, 256, 0, st>>>(h1b, wbuf, cnt, csr, b1, h1m);
    }

    // Layer 2
    {
        dim3 grid(HEADS * OUTF / 64, (N_NODES + 127) / 128);
        gemm_fused_kernel<0, OUTF><<<grid, 256, 0, st>>>(h1m, W2, h2b, att_src2, att_dst2,
                                                         as2, ad2, N_NODES, HEADS * OUTF, HF);
        weight_kernel<<<eblocks, threads, 0, st>>>(src, dst, pos, as2, ad2, wbuf);
        aggregate_kernel<OUTF, false><<<N_NODES, 256, 0, st>>>(h2b, wbuf, cnt, csr, b2, out);
    }
}

// round 12
// speedup vs baseline: 1.1551x; 1.1551x over previous
#include <cuda_runtime.h>
#include <cuda_bf16.h>
#include <mma.h>

using namespace nvcuda;

#define N_NODES 20000
#define N_PAD   20096
#define E_EDGES 640000
#define E_TOT   (E_EDGES + N_NODES)
#define IN_F    256
#define HEADS   8
#define HF      64
#define OUTF    32
#define NEG_SLOPE 0.2f
#define MAXDEG  128

// ------------------- scratch -------------------
__device__ __nv_bfloat16  g_h1b[(size_t)N_PAD * HEADS * HF];
__device__ float          g_h1m[(size_t)N_PAD * HF];
__device__ __nv_bfloat16  g_h2b[(size_t)N_PAD * HEADS * OUTF];
__device__ float g_as1[N_PAD * HEADS];
__device__ float g_ad1[N_PAD * HEADS];
__device__ float g_as2[N_PAD * HEADS];
__device__ float g_ad2[N_PAD * HEADS];
__device__ float g_w[(size_t)N_NODES * MAXDEG * HEADS];
__device__ int   g_cnt[N_NODES];
__device__ int   g_csr[(size_t)N_NODES * MAXDEG];
__device__ int   g_pos[E_TOT];

// ------------------- padded-bucket CSR build -------------------
__global__ void scatter_kernel(const int* __restrict__ src, const int* __restrict__ dst,
                               int* __restrict__ cnt, int* __restrict__ csr,
                               int* __restrict__ pos) {
    int i = blockIdx.x * blockDim.x + threadIdx.x;
    if (i >= E_TOT) return;
    int s, d;
    if (i < E_EDGES) { s = src[i]; d = dst[i]; }
    else             { s = d = i - E_EDGES; }
    int p = atomicAdd(&cnt[d], 1);
    int slot = (p < MAXDEG) ? d * MAXDEG + p : d * MAXDEG;
    csr[slot] = s;
    pos[i] = slot;
}

// ------------------- edge weights (padded slot order) -------------------
__global__ void weight_kernel(const int* __restrict__ src, const int* __restrict__ dst,
                              const int* __restrict__ pos,
                              const float* __restrict__ asrc, const float* __restrict__ adst,
                              float* __restrict__ w) {
    int i = blockIdx.x * blockDim.x + threadIdx.x;
    if (i >= E_TOT) return;
    int s, d;
    if (i < E_EDGES) { s = src[i]; d = dst[i]; }
    else             { s = d = i - E_EDGES; }
    int p = pos[i];
    float4 a0 = __ldg((const float4*)&asrc[s * HEADS]);
    float4 a1 = __ldg((const float4*)&asrc[s * HEADS + 4]);
    float4 d0 = __ldg((const float4*)&adst[d * HEADS]);
    float4 d1 = __ldg((const float4*)&adst[d * HEADS + 4]);
    float e[8] = {a0.x + d0.x, a0.y + d0.y, a0.z + d0.z, a0.w + d0.w,
                  a1.x + d1.x, a1.y + d1.y, a1.z + d1.z, a1.w + d1.w};
    float r[8];
    #pragma unroll
    for (int h = 0; h < 8; h++) {
        float v = e[h];
        v = (v >= 0.f) ? v : NEG_SLOPE * v;
        r[h] = __expf(v);
    }
    float* wp = w + (size_t)p * HEADS;
    *(float4*)wp       = make_float4(r[0], r[1], r[2], r[3]);
    *(float4*)(wp + 4) = make_float4(r[4], r[5], r[6], r[7]);
}

// ------------------- TF32 GEMM + fused logits/bf16 epilogue -------------------
template<int GUARD_A, int CH>
__global__ __launch_bounds__(256, 2)
void gemm_fused_kernel(const float* __restrict__ A, const float* __restrict__ B,
                       __nv_bfloat16* __restrict__ hb,
                       const float* __restrict__ att_src, const float* __restrict__ att_dst,
                       float* __restrict__ asrc, float* __restrict__ adst,
                       int M, int Nn, int K) {
    __shared__ float As[2][128][36];
    __shared__ float Bs[2][32][68];

    const int bm = blockIdx.y * 128;
    const int bn = blockIdx.x * 64;
    const int t = threadIdx.x;
    const int wid = t >> 5;
    const int lane = t & 31;
    const int wm = (wid & 3) * 32;
    const int wn = (wid >> 2) * 32;

    const int ar0 = (t * 4) >> 5;
    const int ac  = (t * 4) & 31;
    const int br0 = (t * 4) >> 6;
    const int bc  = (t * 4) & 63;

    wmma::fragment<wmma::accumulator, 16, 16, 8, float> c[2][2];
    #pragma unroll
    for (int i = 0; i < 2; i++)
        #pragma unroll
        for (int j = 0; j < 2; j++)
            wmma::fill_fragment(c[i][j], 0.0f);

    const int nk = K / 32;

    float4 aR[4], bR[2];
    #pragma unroll
    for (int i = 0; i < 4; i++) {
        int r = ar0 + i * 32;
        if (!GUARD_A || (bm + r) < M)
            aR[i] = *(const float4*)(A + (size_t)(bm + r) * K + ac);
        else
            aR[i] = make_float4(0.f, 0.f, 0.f, 0.f);
    }
    #pragma unroll
    for (int i = 0; i < 2; i++)
        bR[i] = *(const float4*)(B + (size_t)(br0 + i * 16) * Nn + bn + bc);

    #pragma unroll
    for (int i = 0; i < 4; i++) {
        float4 v = aR[i];
        v.x = wmma::__float_to_tf32(v.x); v.y = wmma::__float_to_tf32(v.y);
        v.z = wmma::__float_to_tf32(v.z); v.w = wmma::__float_to_tf32(v.w);
        *(float4*)&As[0][ar0 + i * 32][ac] = v;
    }
    #pragma unroll
    for (int i = 0; i < 2; i++) {
        float4 v = bR[i];
        v.x = wmma::__float_to_tf32(v.x); v.y = wmma::__float_to_tf32(v.y);
        v.z = wmma::__float_to_tf32(v.z); v.w = wmma::__float_to_tf32(v.w);
        *(float4*)&Bs[0][br0 + i * 16][bc] = v;
    }
    __syncthreads();

    for (int kt = 0; kt < nk; kt++) {
        const int cur = kt & 1;
        const int nxt = cur ^ 1;

        if (kt + 1 < nk) {
            int k0 = (kt + 1) * 32;
            #pragma unroll
            for (int i = 0; i < 4; i++) {
                int r = ar0 + i * 32;
                if (!GUARD_A || (bm + r) < M)
                    aR[i] = *(const float4*)(A + (size_t)(bm + r) * K + k0 + ac);
                else
                    aR[i] = make_float4(0.f, 0.f, 0.f, 0.f);
            }
            #pragma unroll
            for (int i = 0; i < 2; i++)
                bR[i] = *(const float4*)(B + (size_t)(k0 + br0 + i * 16) * Nn + bn + bc);
        }

        #pragma unroll
        for (int kk = 0; kk < 4; kk++) {
            wmma::fragment<wmma::matrix_a, 16, 16, 8, wmma::precision::tf32, wmma::row_major> a[2];
            wmma::fragment<wmma::matrix_b, 16, 16, 8, wmma::precision::tf32, wmma::row_major> b[2];
            #pragma unroll
            for (int i = 0; i < 2; i++)
                wmma::load_matrix_sync(a[i], &As[cur][wm + i * 16][kk * 8], 36);
            #pragma unroll
            for (int j = 0; j < 2; j++)
                wmma::load_matrix_sync(b[j], &Bs[cur][kk * 8][wn + j * 16], 68);
            #pragma unroll
            for (int i = 0; i < 2; i++)
                #pragma unroll
                for (int j = 0; j < 2; j++)
                    wmma::mma_sync(c[i][j], a[i], b[j], c[i][j]);
        }

        if (kt + 1 < nk) {
            #pragma unroll
            for (int i = 0; i < 4; i++) {
                float4 v = aR[i];
                v.x = wmma::__float_to_tf32(v.x); v.y = wmma::__float_to_tf32(v.y);
                v.z = wmma::__float_to_tf32(v.z); v.w = wmma::__float_to_tf32(v.w);
                *(float4*)&As[nxt][ar0 + i * 32][ac] = v;
            }
            #pragma unroll
            for (int i = 0; i < 2; i++) {
                float4 v = bR[i];
                v.x = wmma::__float_to_tf32(v.x); v.y = wmma::__float_to_tf32(v.y);
                v.z = wmma::__float_to_tf32(v.z); v.w = wmma::__float_to_tf32(v.w);
                *(float4*)&Bs[nxt][br0 + i * 16][bc] = v;
            }
        }
        __syncthreads();
    }

    float (*Cs)[68] = reinterpret_cast<float(*)[68]>(&As[0][0][0]);
    #pragma unroll
    for (int i = 0; i < 2; i++)
        #pragma unroll
        for (int j = 0; j < 2; j++)
            wmma::store_matrix_sync(&Cs[wm + i * 16][wn + j * 16], c[i][j], 68,
                                    wmma::mem_row_major);
    __syncthreads();

    const float a_s0 = __ldg(att_src + bn + lane * 2);
    const float a_s1 = __ldg(att_src + bn + lane * 2 + 1);
    const float a_d0 = __ldg(att_dst + bn + lane * 2);
    const float a_d1 = __ldg(att_dst + bn + lane * 2 + 1);

    #pragma unroll
    for (int rr = 0; rr < 16; rr++) {
        int r = wid * 16 + rr;
        float2 v = *(const float2*)&Cs[r][lane * 2];
        ((__nv_bfloat162*)(hb + (size_t)(bm + r) * Nn + bn))[lane] =
            __floats2bfloat162_rn(v.x, v.y);
        float s1 = v.x * a_s0 + v.y * a_s1;
        float s2 = v.x * a_d0 + v.y * a_d1;
        if (CH == 64) {
            #pragma unroll
            for (int o = 16; o > 0; o >>= 1) {
                s1 += __shfl_xor_sync(0xffffffffu, s1, o);
                s2 += __shfl_xor_sync(0xffffffffu, s2, o);
            }
            if (lane == 0) {
                int head = bn >> 6;
                asrc[(bm + r) * HEADS + head] = s1;
                adst[(bm + r) * HEADS + head] = s2;
            }
        } else {
            #pragma unroll
            for (int o = 8; o > 0; o >>= 1) {
                s1 += __shfl_xor_sync(0xffffffffu, s1, o);
                s2 += __shfl_xor_sync(0xffffffffu, s2, o);
            }
            if ((lane & 15) == 0) {
                int head = (bn >> 5) + (lane >> 4);
                asrc[(bm + r) * HEADS + head] = s1;
                adst[(bm + r) * HEADS + head] = s2;
            }
        }
    }
}

// ------------------- GAT aggregation (R9 geometry + FFMA2 inner loop) ----------
// C=64 (L1): warp covers 4 heads (lane -> head 4*(wid&1)+(lane>>3), 8 chans,
//   one LDG.128 per lane); 8 warps = 2 head-halves x 4 edge-quarters (NQ=4).
// C=32 (L2): warp covers all 8 heads (lane -> head lane>>2, 8 chans, LDG.128);
//   8 warps = 8 edge-eighths (NQ=8).
// Accumulate via packed fma.rn.f32x2; bf16->f32 by shift/mask (no CVT).
template <int C, bool RELU>
__global__ __launch_bounds__(256)
void aggregate_kernel(const __nv_bfloat16* __restrict__ h, const float* __restrict__ w,
                      const int* __restrict__ cnt, const int* __restrict__ csr,
                      const float* __restrict__ bias, float* __restrict__ out) {
    constexpr int NQ = (C == 64) ? 4 : 8;
    const int node = blockIdx.x;
    const int wid = threadIdx.x >> 5;
    const int lane = threadIdx.x & 31;

    int head, cbase, q;
    if (C == 64) {
        q = wid >> 1;
        head = 4 * (wid & 1) + (lane >> 3);
        cbase = (lane & 7) * 8;
    } else {
        q = wid;
        head = lane >> 2;
        cbase = (lane & 3) * 8;
    }

    const int len = min(cnt[node], MAXDEG);
    const int chunk = (len + NQ - 1) / NQ;
    const int lo = node * MAXDEG + min(len, q * chunk);
    const int hi = node * MAXDEG + min(len, q * chunk + chunk);

    const unsigned rowBytes = (unsigned)(C * HEADS * 2);   // 1024 / 512
    const unsigned laneOff  = (unsigned)(head * C + cbase) * 2u;
    const char* hbase = (const char*)h;

    float den = 0.f;
    unsigned long long acc2[4];
    #pragma unroll
    for (int v = 0; v < 4; v++) acc2[v] = 0ULL;

    #pragma unroll 2
    for (int j = lo; j < hi; j++) {
        int s = __ldg(&csr[j]);
        float wj = __ldg(&w[j * HEADS + head]);
        den += wj;
        unsigned long long wj2;
        asm("mov.b64 %0, {%1, %1};" : "=l"(wj2) : "f"(wj));
        unsigned off = (unsigned)s * rowBytes + laneOff;
        uint4 raw = __ldg((const uint4*)(hbase + off));
        unsigned raws[4] = {raw.x, raw.y, raw.z, raw.w};
        #pragma unroll
        for (int k = 0; k < 4; k++) {
            unsigned lo32 = raws[k] << 16;
            unsigned hi32 = raws[k] & 0xffff0000u;
            unsigned long long hv;
            asm("mov.b64 %0, {%1, %2};" : "=l"(hv) : "r"(lo32), "r"(hi32));
            asm("fma.rn.f32x2 %0, %1, %2, %0;" : "+l"(acc2[k]) : "l"(hv), "l"(wj2));
        }
    }

    __shared__ float sacc[NQ][HEADS][C];
    __shared__ float sden[NQ][HEADS];
    #pragma unroll
    for (int k = 0; k < 4; k++) {
        float a0, a1;
        asm("mov.b64 {%0, %1}, %2;" : "=f"(a0), "=f"(a1) : "l"(acc2[k]));
        sacc[q][head][cbase + 2 * k]     = a0;
        sacc[q][head][cbase + 2 * k + 1] = a1;
    }
    if (cbase == 0) sden[q][head] = den;
    __syncthreads();

    if (threadIdx.x < C) {
        int cc = threadIdx.x;
        float sum = 0.f;
        #pragma unroll
        for (int hh = 0; hh < HEADS; hh++) {
            float a = 0.f, d = 0.f;
            #pragma unroll
            for (int qq = 0; qq < NQ; qq++) {
                a += sacc[qq][hh][cc];
                d += sden[qq][hh];
            }
            sum += a / d;
        }
        sum = sum * (1.0f / HEADS) + bias[cc];
        if (RELU) sum = fmaxf(sum, 0.f);
        out[(size_t)node * C + cc] = sum;
    }
}

// ------------------- launch -------------------
extern "C" void kernel_launch(void* const* d_in, const int* in_sizes, int n_in,
                              void* d_out, int out_size) {
    const float* x        = (const float*)d_in[0];
    const int*   ei       = (const int*)  d_in[1];
    const float* W1       = (const float*)d_in[2];
    const float* att_src1 = (const float*)d_in[3];
    const float* att_dst1 = (const float*)d_in[4];
    const float* b1       = (const float*)d_in[5];
    const float* W2       = (const float*)d_in[6];
    const float* att_src2 = (const float*)d_in[7];
    const float* att_dst2 = (const float*)d_in[8];
    const float* b2       = (const float*)d_in[9];
    float* out = (float*)d_out;

    const int* src = ei;
    const int* dst = ei + E_EDGES;

    float *h1m, *as1, *ad1, *as2, *ad2, *wbuf;
    __nv_bfloat16 *h1b, *h2b;
    int *cnt, *csr, *pos;
    cudaGetSymbolAddress((void**)&h1b,  g_h1b);
    cudaGetSymbolAddress((void**)&h1m,  g_h1m);
    cudaGetSymbolAddress((void**)&h2b,  g_h2b);
    cudaGetSymbolAddress((void**)&as1,  g_as1);
    cudaGetSymbolAddress((void**)&ad1,  g_ad1);
    cudaGetSymbolAddress((void**)&as2,  g_as2);
    cudaGetSymbolAddress((void**)&ad2,  g_ad2);
    cudaGetSymbolAddress((void**)&wbuf, g_w);
    cudaGetSymbolAddress((void**)&cnt,  g_cnt);
    cudaGetSymbolAddress((void**)&csr,  g_csr);
    cudaGetSymbolAddress((void**)&pos,  g_pos);

    cudaStream_t st = 0;
    const int threads = 256;
    const int eblocks = (E_TOT + threads - 1) / threads;

    cudaMemsetAsync(cnt, 0, N_NODES * sizeof(int), st);
    scatter_kernel<<<eblocks, threads, 0, st>>>(src, dst, cnt, csr, pos);

    // Layer 1
    {
        dim3 grid(HEADS * HF / 64, (N_NODES + 127) / 128);
        gemm_fused_kernel<1, HF><<<grid, 256, 0, st>>>(x, W1, h1b, att_src1, att_dst1,
                                                       as1, ad1, N_NODES, HEADS * HF, IN_F);
        weight_kernel<<<eblocks, threads, 0, st>>>(src, dst, pos, as1, ad1, wbuf);
        aggregate_kernel<HF, true><<<N_NODES, 256, 0, st>>>(h1b, wbuf, cnt, csr, b1, h1m);
    }

    // Layer 2
    {
        dim3 grid(HEADS * OUTF / 64, (N_NODES + 127) / 128);
        gemm_fused_kernel<0, OUTF><<<grid, 256, 0, st>>>(h1m, W2, h2b, att_src2, att_dst2,
                                                         as2, ad2, N_NODES, HEADS * OUTF, HF);
        weight_kernel<<<eblocks, threads, 0, st>>>(src, dst, pos, as2, ad2, wbuf);
        aggregate_kernel<OUTF, false><<<N_NODES, 256, 0, st>>>(h2b, wbuf, cnt, csr, b2, out);
    }
}

// round 13
// speedup vs baseline: 1.4640x; 1.2674x over previous
#include <cuda_runtime.h>
#include <cuda_bf16.h>
#include <cuda_fp16.h>
#include <mma.h>

using namespace nvcuda;

#define N_NODES 20000
#define N_PAD   20096
#define E_EDGES 640000
#define E_TOT   (E_EDGES + N_NODES)
#define IN_F    256
#define HEADS   8
#define HF      64
#define OUTF    32
#define NEG_SLOPE 0.2f
#define MAXDEG  128

// ------------------- scratch -------------------
__device__ __nv_bfloat16  g_h1b[(size_t)N_PAD * HEADS * HF];
__device__ float          g_h1m[(size_t)N_PAD * HF];
__device__ __nv_bfloat16  g_h2b[(size_t)N_PAD * HEADS * OUTF];
__device__ float g_as1[N_PAD * HEADS];
__device__ float g_ad1[N_PAD * HEADS];
__device__ float g_as2[N_PAD * HEADS];
__device__ float g_ad2[N_PAD * HEADS];
__device__ float g_w[(size_t)N_NODES * MAXDEG * HEADS];
__device__ int   g_cnt[N_NODES];
__device__ int   g_csr[(size_t)N_NODES * MAXDEG];
__device__ int   g_pos[E_TOT];

// ------------------- padded-bucket CSR build -------------------
__global__ void scatter_kernel(const int* __restrict__ src, const int* __restrict__ dst,
                               int* __restrict__ cnt, int* __restrict__ csr,
                               int* __restrict__ pos) {
    int i = blockIdx.x * blockDim.x + threadIdx.x;
    if (i >= E_TOT) return;
    int s, d;
    if (i < E_EDGES) { s = src[i]; d = dst[i]; }
    else             { s = d = i - E_EDGES; }
    int p = atomicAdd(&cnt[d], 1);
    int slot = (p < MAXDEG) ? d * MAXDEG + p : d * MAXDEG;
    csr[slot] = s;
    pos[i] = slot;
}

// ------------------- edge weights (padded slot order) -------------------
__global__ void weight_kernel(const int* __restrict__ src, const int* __restrict__ dst,
                              const int* __restrict__ pos,
                              const float* __restrict__ asrc, const float* __restrict__ adst,
                              float* __restrict__ w) {
    int i = blockIdx.x * blockDim.x + threadIdx.x;
    if (i >= E_TOT) return;
    int s, d;
    if (i < E_EDGES) { s = src[i]; d = dst[i]; }
    else             { s = d = i - E_EDGES; }
    int p = pos[i];
    float4 a0 = __ldg((const float4*)&asrc[s * HEADS]);
    float4 a1 = __ldg((const float4*)&asrc[s * HEADS + 4]);
    float4 d0 = __ldg((const float4*)&adst[d * HEADS]);
    float4 d1 = __ldg((const float4*)&adst[d * HEADS + 4]);
    float e[8] = {a0.x + d0.x, a0.y + d0.y, a0.z + d0.z, a0.w + d0.w,
                  a1.x + d1.x, a1.y + d1.y, a1.z + d1.z, a1.w + d1.w};
    float r[8];
    #pragma unroll
    for (int h = 0; h < 8; h++) {
        float v = e[h];
        v = (v >= 0.f) ? v : NEG_SLOPE * v;
        r[h] = __expf(v);
    }
    float* wp = w + (size_t)p * HEADS;
    *(float4*)wp       = make_float4(r[0], r[1], r[2], r[3]);
    *(float4*)(wp + 4) = make_float4(r[4], r[5], r[6], r[7]);
}

// ------------------- fp16 tensor-core GEMM + fused logits/bf16 epilogue ----------
// Block tile 128(M) x 64(N), BK=32 (2 x k16), double-buffered half smem, 2 CTAs/SM.
// Inputs converted fp32->fp16 at smem store; fp32 accumulate (HMMA.16816.F32).
#define SMEM_BYTES 34816                     // 128*68*4 (Cs) >= As(20480)+Bs(9216)
#define AS_OFF 0
#define BS_OFF 20480

template<int GUARD_A, int CH>
__global__ __launch_bounds__(256, 2)
void gemm_fused_kernel(const float* __restrict__ A, const float* __restrict__ B,
                       __nv_bfloat16* __restrict__ hb,
                       const float* __restrict__ att_src, const float* __restrict__ att_dst,
                       float* __restrict__ asrc, float* __restrict__ adst,
                       int M, int Nn, int K) {
    __shared__ __align__(16) char smem_raw[SMEM_BYTES];
    typedef __half (*AsT)[128][40];
    typedef __half (*BsT)[32][72];
    AsT As = reinterpret_cast<AsT>(smem_raw + AS_OFF);
    BsT Bs = reinterpret_cast<BsT>(smem_raw + BS_OFF);

    const int bm = blockIdx.y * 128;
    const int bn = blockIdx.x * 64;
    const int t = threadIdx.x;
    const int wid = t >> 5;
    const int lane = t & 31;
    const int wm = (wid & 3) * 32;
    const int wn = (wid >> 2) * 32;

    const int ar0 = (t * 4) >> 5;      // A: 4 rows/thread (+32 each), 4 cols
    const int ac  = (t * 4) & 31;
    const int br0 = (t * 4) >> 6;      // B: 2 rows/thread (+16 each), 4 cols
    const int bc  = (t * 4) & 63;

    wmma::fragment<wmma::accumulator, 16, 16, 16, float> c[2][2];
    #pragma unroll
    for (int i = 0; i < 2; i++)
        #pragma unroll
        for (int j = 0; j < 2; j++)
            wmma::fill_fragment(c[i][j], 0.0f);

    const int nk = K / 32;

    float4 aR[4], bR[2];
    #pragma unroll
    for (int i = 0; i < 4; i++) {
        int r = ar0 + i * 32;
        if (!GUARD_A || (bm + r) < M)
            aR[i] = *(const float4*)(A + (size_t)(bm + r) * K + ac);
        else
            aR[i] = make_float4(0.f, 0.f, 0.f, 0.f);
    }
    #pragma unroll
    for (int i = 0; i < 2; i++)
        bR[i] = *(const float4*)(B + (size_t)(br0 + i * 16) * Nn + bn + bc);

    // store chunk 0 as fp16
    #pragma unroll
    for (int i = 0; i < 4; i++) {
        union { uint2 u; __half2 h[2]; } pk;
        pk.h[0] = __floats2half2_rn(aR[i].x, aR[i].y);
        pk.h[1] = __floats2half2_rn(aR[i].z, aR[i].w);
        *(uint2*)&As[0][ar0 + i * 32][ac] = pk.u;
    }
    #pragma unroll
    for (int i = 0; i < 2; i++) {
        union { uint2 u; __half2 h[2]; } pk;
        pk.h[0] = __floats2half2_rn(bR[i].x, bR[i].y);
        pk.h[1] = __floats2half2_rn(bR[i].z, bR[i].w);
        *(uint2*)&Bs[0][br0 + i * 16][bc] = pk.u;
    }
    __syncthreads();

    for (int kt = 0; kt < nk; kt++) {
        const int cur = kt & 1;
        const int nxt = cur ^ 1;

        if (kt + 1 < nk) {
            int k0 = (kt + 1) * 32;
            #pragma unroll
            for (int i = 0; i < 4; i++) {
                int r = ar0 + i * 32;
                if (!GUARD_A || (bm + r) < M)
                    aR[i] = *(const float4*)(A + (size_t)(bm + r) * K + k0 + ac);
                else
                    aR[i] = make_float4(0.f, 0.f, 0.f, 0.f);
            }
            #pragma unroll
            for (int i = 0; i < 2; i++)
                bR[i] = *(const float4*)(B + (size_t)(k0 + br0 + i * 16) * Nn + bn + bc);
        }

        #pragma unroll
        for (int kk = 0; kk < 2; kk++) {
            wmma::fragment<wmma::matrix_a, 16, 16, 16, __half, wmma::row_major> a[2];
            wmma::fragment<wmma::matrix_b, 16, 16, 16, __half, wmma::row_major> b[2];
            #pragma unroll
            for (int i = 0; i < 2; i++)
                wmma::load_matrix_sync(a[i], &As[cur][wm + i * 16][kk * 16], 40);
            #pragma unroll
            for (int j = 0; j < 2; j++)
                wmma::load_matrix_sync(b[j], &Bs[cur][kk * 16][wn + j * 16], 72);
            #pragma unroll
            for (int i = 0; i < 2; i++)
                #pragma unroll
                for (int j = 0; j < 2; j++)
                    wmma::mma_sync(c[i][j], a[i], b[j], c[i][j]);
        }

        if (kt + 1 < nk) {
            #pragma unroll
            for (int i = 0; i < 4; i++) {
                union { uint2 u; __half2 h[2]; } pk;
                pk.h[0] = __floats2half2_rn(aR[i].x, aR[i].y);
                pk.h[1] = __floats2half2_rn(aR[i].z, aR[i].w);
                *(uint2*)&As[nxt][ar0 + i * 32][ac] = pk.u;
            }
            #pragma unroll
            for (int i = 0; i < 2; i++) {
                union { uint2 u; __half2 h[2]; } pk;
                pk.h[0] = __floats2half2_rn(bR[i].x, bR[i].y);
                pk.h[1] = __floats2half2_rn(bR[i].z, bR[i].w);
                *(uint2*)&Bs[nxt][br0 + i * 16][bc] = pk.u;
            }
        }
        __syncthreads();
    }

    // ---- epilogue: stage C in smem (aliases tile buffers), bf16 store + logits ----
    float (*Cs)[68] = reinterpret_cast<float(*)[68]>(smem_raw);
    #pragma unroll
    for (int i = 0; i < 2; i++)
        #pragma unroll
        for (int j = 0; j < 2; j++)
            wmma::store_matrix_sync(&Cs[wm + i * 16][wn + j * 16], c[i][j], 68,
                                    wmma::mem_row_major);
    __syncthreads();

    const float a_s0 = __ldg(att_src + bn + lane * 2);
    const float a_s1 = __ldg(att_src + bn + lane * 2 + 1);
    const float a_d0 = __ldg(att_dst + bn + lane * 2);
    const float a_d1 = __ldg(att_dst + bn + lane * 2 + 1);

    #pragma unroll
    for (int rr = 0; rr < 16; rr++) {
        int r = wid * 16 + rr;
        float2 v = *(const float2*)&Cs[r][lane * 2];
        ((__nv_bfloat162*)(hb + (size_t)(bm + r) * Nn + bn))[lane] =
            __floats2bfloat162_rn(v.x, v.y);
        float s1 = v.x * a_s0 + v.y * a_s1;
        float s2 = v.x * a_d0 + v.y * a_d1;
        if (CH == 64) {
            #pragma unroll
            for (int o = 16; o > 0; o >>= 1) {
                s1 += __shfl_xor_sync(0xffffffffu, s1, o);
                s2 += __shfl_xor_sync(0xffffffffu, s2, o);
            }
            if (lane == 0) {
                int head = bn >> 6;
                asrc[(bm + r) * HEADS + head] = s1;
                adst[(bm + r) * HEADS + head] = s2;
            }
        } else {
            #pragma unroll
            for (int o = 8; o > 0; o >>= 1) {
                s1 += __shfl_xor_sync(0xffffffffu, s1, o);
                s2 += __shfl_xor_sync(0xffffffffu, s2, o);
            }
            if ((lane & 15) == 0) {
                int head = (bn >> 5) + (lane >> 4);
                asrc[(bm + r) * HEADS + head] = s1;
                adst[(bm + r) * HEADS + head] = s2;
            }
        }
    }
}

// ------------------- GAT aggregation (R9 geometry + FFMA2 inner loop) ----------
template <int C, bool RELU>
__global__ __launch_bounds__(256)
void aggregate_kernel(const __nv_bfloat16* __restrict__ h, const float* __restrict__ w,
                      const int* __restrict__ cnt, const int* __restrict__ csr,
                      const float* __restrict__ bias, float* __restrict__ out) {
    constexpr int NQ = (C == 64) ? 4 : 8;
    const int node = blockIdx.x;
    const int wid = threadIdx.x >> 5;
    const int lane = threadIdx.x & 31;

    int head, cbase, q;
    if (C == 64) {
        q = wid >> 1;
        head = 4 * (wid & 1) + (lane >> 3);
        cbase = (lane & 7) * 8;
    } else {
        q = wid;
        head = lane >> 2;
        cbase = (lane & 3) * 8;
    }

    const int len = min(cnt[node], MAXDEG);
    const int chunk = (len + NQ - 1) / NQ;
    const int lo = node * MAXDEG + min(len, q * chunk);
    const int hi = node * MAXDEG + min(len, q * chunk + chunk);

    const unsigned rowBytes = (unsigned)(C * HEADS * 2);
    const unsigned laneOff  = (unsigned)(head * C + cbase) * 2u;
    const char* hbase = (const char*)h;

    float den = 0.f;
    unsigned long long acc2[4];
    #pragma unroll
    for (int v = 0; v < 4; v++) acc2[v] = 0ULL;

    #pragma unroll 2
    for (int j = lo; j < hi; j++) {
        int s = __ldg(&csr[j]);
        float wj = __ldg(&w[j * HEADS + head]);
        den += wj;
        unsigned long long wj2;
        asm("mov.b64 %0, {%1, %1};" : "=l"(wj2) : "f"(wj));
        unsigned off = (unsigned)s * rowBytes + laneOff;
        uint4 raw = __ldg((const uint4*)(hbase + off));
        unsigned raws[4] = {raw.x, raw.y, raw.z, raw.w};
        #pragma unroll
        for (int k = 0; k < 4; k++) {
            unsigned lo32 = raws[k] << 16;
            unsigned hi32 = raws[k] & 0xffff0000u;
            unsigned long long hv;
            asm("mov.b64 %0, {%1, %2};" : "=l"(hv) : "r"(lo32), "r"(hi32));
            asm("fma.rn.f32x2 %0, %1, %2, %0;" : "+l"(acc2[k]) : "l"(hv), "l"(wj2));
        }
    }

    __shared__ float sacc[NQ][HEADS][C];
    __shared__ float sden[NQ][HEADS];
    #pragma unroll
    for (int k = 0; k < 4; k++) {
        float a0, a1;
        asm("mov.b64 {%0, %1}, %2;" : "=f"(a0), "=f"(a1) : "l"(acc2[k]));
        sacc[q][head][cbase + 2 * k]     = a0;
        sacc[q][head][cbase + 2 * k + 1] = a1;
    }
    if (cbase == 0) sden[q][head] = den;
    __syncthreads();

    if (threadIdx.x < C) {
        int cc = threadIdx.x;
        float sum = 0.f;
        #pragma unroll
        for (int hh = 0; hh < HEADS; hh++) {
            float a = 0.f, d = 0.f;
            #pragma unroll
            for (int qq = 0; qq < NQ; qq++) {
                a += sacc[qq][hh][cc];
                d += sden[qq][hh];
            }
            sum += a / d;
        }
        sum = sum * (1.0f / HEADS) + bias[cc];
        if (RELU) sum = fmaxf(sum, 0.f);
        out[(size_t)node * C + cc] = sum;
    }
}

// ------------------- launch -------------------
extern "C" void kernel_launch(void* const* d_in, const int* in_sizes, int n_in,
                              void* d_out, int out_size) {
    const float* x        = (const float*)d_in[0];
    const int*   ei       = (const int*)  d_in[1];
    const float* W1       = (const float*)d_in[2];
    const float* att_src1 = (const float*)d_in[3];
    const float* att_dst1 = (const float*)d_in[4];
    const float* b1       = (const float*)d_in[5];
    const float* W2       = (const float*)d_in[6];
    const float* att_src2 = (const float*)d_in[7];
    const float* att_dst2 = (const float*)d_in[8];
    const float* b2       = (const float*)d_in[9];
    float* out = (float*)d_out;

    const int* src = ei;
    const int* dst = ei + E_EDGES;

    float *h1m, *as1, *ad1, *as2, *ad2, *wbuf;
    __nv_bfloat16 *h1b, *h2b;
    int *cnt, *csr, *pos;
    cudaGetSymbolAddress((void**)&h1b,  g_h1b);
    cudaGetSymbolAddress((void**)&h1m,  g_h1m);
    cudaGetSymbolAddress((void**)&h2b,  g_h2b);
    cudaGetSymbolAddress((void**)&as1,  g_as1);
    cudaGetSymbolAddress((void**)&ad1,  g_ad1);
    cudaGetSymbolAddress((void**)&as2,  g_as2);
    cudaGetSymbolAddress((void**)&ad2,  g_ad2);
    cudaGetSymbolAddress((void**)&wbuf, g_w);
    cudaGetSymbolAddress((void**)&cnt,  g_cnt);
    cudaGetSymbolAddress((void**)&csr,  g_csr);
    cudaGetSymbolAddress((void**)&pos,  g_pos);

    cudaStream_t st = 0;
    const int threads = 256;
    const int eblocks = (E_TOT + threads - 1) / threads;

    cudaMemsetAsync(cnt, 0, N_NODES * sizeof(int), st);
    scatter_kernel<<<eblocks, threads, 0, st>>>(src, dst, cnt, csr, pos);

    // Layer 1
    {
        dim3 grid(HEADS * HF / 64, (N_NODES + 127) / 128);
        gemm_fused_kernel<1, HF><<<grid, 256, 0, st>>>(x, W1, h1b, att_src1, att_dst1,
                                                       as1, ad1, N_NODES, HEADS * HF, IN_F);
        weight_kernel<<<eblocks, threads, 0, st>>>(src, dst, pos, as1, ad1, wbuf);
        aggregate_kernel<HF, true><<<N_NODES, 256, 0, st>>>(h1b, wbuf, cnt, csr, b1, h1m);
    }

    // Layer 2
    {
        dim3 grid(HEADS * OUTF / 64, (N_NODES + 127) / 128);
        gemm_fused_kernel<0, OUTF><<<grid, 256, 0, st>>>(h1m, W2, h2b, att_src2, att_dst2,
                                                         as2, ad2, N_NODES, HEADS * OUTF, HF);
        weight_kernel<<<eblocks, threads, 0, st>>>(src, dst, pos, as2, ad2, wbuf);
        aggregate_kernel<OUTF, false><<<N_NODES, 256, 0, st>>>(h2b, wbuf, cnt, csr, b2, out);
    }
}

// round 17
// speedup vs baseline: 1.5238x; 1.0409x over previous
#include <cuda_runtime.h>
#include <cuda_bf16.h>
#include <cuda_fp16.h>
#include <mma.h>

using namespace nvcuda;

#define N_NODES 20000
#define N_PAD   20096
#define E_EDGES 640000
#define E_TOT   (E_EDGES + N_NODES)
#define IN_F    256
#define HEADS   8
#define HF      64
#define OUTF    32
#define NEG_SLOPE 0.2f
#define MAXDEG  128

// ------------------- scratch -------------------
__device__ __half         g_xh[(size_t)N_PAD * IN_F];          // fp16 x (padded rows stay 0)
__device__ __half         g_w1h[IN_F * HEADS * HF];
__device__ __half         g_w2h[HF * HEADS * OUTF];
__device__ __nv_bfloat16  g_h1b[(size_t)N_PAD * HEADS * HF];
__device__ __half         g_h1mh[(size_t)N_PAD * HF];          // fp16 h1m (padded rows stay 0)
__device__ __nv_bfloat16  g_h2b[(size_t)N_PAD * HEADS * OUTF];
__device__ float g_as1[N_PAD * HEADS];
__device__ float g_ad1[N_PAD * HEADS];
__device__ float g_as2[N_PAD * HEADS];
__device__ float g_ad2[N_PAD * HEADS];
__device__ float g_w[(size_t)N_NODES * MAXDEG * HEADS];
__device__ int   g_cnt[N_NODES];
__device__ int   g_csr[(size_t)N_NODES * MAXDEG];
__device__ int   g_pos[E_TOT];

// ------------------- fp32 -> fp16 convert (x, W1, W2 in one kernel) -------------
#define NX4  (N_NODES * IN_F / 4)
#define NW14 (IN_F * HEADS * HF / 4)
#define NW24 (HF * HEADS * OUTF / 4)
__global__ void convert_kernel(const float* __restrict__ x, const float* __restrict__ W1,
                               const float* __restrict__ W2, __half* __restrict__ xh,
                               __half* __restrict__ w1h, __half* __restrict__ w2h) {
    int i = blockIdx.x * blockDim.x + threadIdx.x;
    const float* src; __half* dst; int idx;
    if (i < NX4)                { src = x;  dst = xh;  idx = i; }
    else if (i < NX4 + NW14)    { src = W1; dst = w1h; idx = i - NX4; }
    else if (i < NX4 + NW14 + NW24) { src = W2; dst = w2h; idx = i - NX4 - NW14; }
    else return;
    float4 v = __ldg((const float4*)src + idx);
    union { uint2 u; __half2 h[2]; } pk;
    pk.h[0] = __floats2half2_rn(v.x, v.y);
    pk.h[1] = __floats2half2_rn(v.z, v.w);
    ((uint2*)dst)[idx] = pk.u;
}

// ------------------- padded-bucket CSR build -------------------
__global__ void scatter_kernel(const int* __restrict__ src, const int* __restrict__ dst,
                               int* __restrict__ cnt, int* __restrict__ csr,
                               int* __restrict__ pos) {
    int i = blockIdx.x * blockDim.x + threadIdx.x;
    if (i >= E_TOT) return;
    int s, d;
    if (i < E_EDGES) { s = src[i]; d = dst[i]; }
    else             { s = d = i - E_EDGES; }
    int p = atomicAdd(&cnt[d], 1);
    int slot = (p < MAXDEG) ? d * MAXDEG + p : d * MAXDEG;
    csr[slot] = s;
    pos[i] = slot;
}

// ------------------- edge weights (padded slot order) -------------------
__global__ void weight_kernel(const int* __restrict__ src, const int* __restrict__ dst,
                              const int* __restrict__ pos,
                              const float* __restrict__ asrc, const float* __restrict__ adst,
                              float* __restrict__ w) {
    int i = blockIdx.x * blockDim.x + threadIdx.x;
    if (i >= E_TOT) return;
    int s, d;
    if (i < E_EDGES) { s = src[i]; d = dst[i]; }
    else             { s = d = i - E_EDGES; }
    int p = pos[i];
    float4 a0 = __ldg((const float4*)&asrc[s * HEADS]);
    float4 a1 = __ldg((const float4*)&asrc[s * HEADS + 4]);
    float4 d0 = __ldg((const float4*)&adst[d * HEADS]);
    float4 d1 = __ldg((const float4*)&adst[d * HEADS + 4]);
    float e[8] = {a0.x + d0.x, a0.y + d0.y, a0.z + d0.z, a0.w + d0.w,
                  a1.x + d1.x, a1.y + d1.y, a1.z + d1.z, a1.w + d1.w};
    float r[8];
    #pragma unroll
    for (int h = 0; h < 8; h++) {
        float v = e[h];
        v = (v >= 0.f) ? v : NEG_SLOPE * v;
        r[h] = __expf(v);
    }
    float* wp = w + (size_t)p * HEADS;
    *(float4*)wp       = make_float4(r[0], r[1], r[2], r[3]);
    *(float4*)(wp + 4) = make_float4(r[4], r[5], r[6], r[7]);
}

// ------------------- fp16 GEMM 128x128, cp.async, fused logits/bf16 epilogue -----
// A[N_PAD x K] fp16, B[K x Nn] fp16 (both pre-converted; no guards needed).
// 8 warps: 4(m) x 2(n); warp tile 32x64 = 2x4 m16n16k16 frags. BK=32, 2-stage.
// Epilogue: two 64-col passes staged in tile smem; bf16 h store + logits dots.
#define AS_STRIDE 40
#define BS_STRIDE 136
#define AS_BYTES (2 * 128 * AS_STRIDE * 2)   // 20480
#define BS_BYTES (2 * 32 * BS_STRIDE * 2)    // 17408
#define GEMM_SMEM (AS_BYTES + BS_BYTES)      // 37888 (Cs 128x68x4=34816 fits)

__device__ __forceinline__ void cp16(void* smem, const void* gmem) {
    unsigned saddr = (unsigned)__cvta_generic_to_shared(smem);
    asm volatile("cp.async.cg.shared.global [%0], [%1], 16;" :: "r"(saddr), "l"(gmem));
}

template<int CH>
__global__ __launch_bounds__(256, 2)
void gemm_fused_kernel(const __half* __restrict__ A, const __half* __restrict__ B,
                       __nv_bfloat16* __restrict__ hb,
                       const float* __restrict__ att_src, const float* __restrict__ att_dst,
                       float* __restrict__ asrc, float* __restrict__ adst,
                       int Nn, int K) {
    __shared__ __align__(16) char smem_raw[GEMM_SMEM];
    typedef __half (*AsT)[128][AS_STRIDE];
    typedef __half (*BsT)[32][BS_STRIDE];
    AsT As = reinterpret_cast<AsT>(smem_raw);
    BsT Bs = reinterpret_cast<BsT>(smem_raw + AS_BYTES);

    const int bm = blockIdx.y * 128;
    const int bn = blockIdx.x * 128;
    const int t = threadIdx.x;
    const int wid = t >> 5;
    const int lane = t & 31;
    const int wm = (wid & 3) * 32;
    const int wn = (wid >> 2) * 64;

    const int nk = K / 32;

    // cp.async mappings: 512 16B-chunks each for A and B, 2 per thread.
    // A chunk c: row = c>>2, col8 = c&3.  B chunk c: row = c>>4, col8 = c&15.
    wmma::fragment<wmma::accumulator, 16, 16, 16, float> c[2][4];
    #pragma unroll
    for (int i = 0; i < 2; i++)
        #pragma unroll
        for (int j = 0; j < 4; j++)
            wmma::fill_fragment(c[i][j], 0.0f);

    auto issue = [&](int kt, int buf) {
        int k0 = kt * 32;
        #pragma unroll
        for (int r = 0; r < 2; r++) {
            int ca = t + r * 256;
            int arow = ca >> 2, ac8 = ca & 3;
            cp16(&As[buf][arow][ac8 * 8], A + (size_t)(bm + arow) * K + k0 + ac8 * 8);
            int brow = ca >> 4, bc8 = ca & 15;
            cp16(&Bs[buf][brow][bc8 * 8], B + (size_t)(k0 + brow) * Nn + bn + bc8 * 8);
        }
    };

    issue(0, 0);
    asm volatile("cp.async.commit_group;");

    for (int kt = 0; kt < nk; kt++) {
        const int cur = kt & 1;
        if (kt + 1 < nk) {
            issue(kt + 1, cur ^ 1);
            asm volatile("cp.async.commit_group;");
            asm volatile("cp.async.wait_group 1;");
        } else {
            asm volatile("cp.async.wait_group 0;");
        }
        __syncthreads();

        #pragma unroll
        for (int kk = 0; kk < 2; kk++) {
            wmma::fragment<wmma::matrix_a, 16, 16, 16, __half, wmma::row_major> a[2];
            #pragma unroll
            for (int i = 0; i < 2; i++)
                wmma::load_matrix_sync(a[i], &As[cur][wm + i * 16][kk * 16], AS_STRIDE);
            #pragma unroll
            for (int j = 0; j < 4; j++) {
                wmma::fragment<wmma::matrix_b, 16, 16, 16, __half, wmma::row_major> b;
                wmma::load_matrix_sync(b, &Bs[cur][kk * 16][wn + j * 16], BS_STRIDE);
                wmma::mma_sync(c[0][j], a[0], b, c[0][j]);
                wmma::mma_sync(c[1][j], a[1], b, c[1][j]);
            }
        }
        __syncthreads();
    }

    // ---- epilogue: two 64-col passes ----
    float (*Cs)[68] = reinterpret_cast<float(*)[68]>(smem_raw);
    #pragma unroll
    for (int pass = 0; pass < 2; pass++) {
        if ((wid >> 2) == pass) {
            #pragma unroll
            for (int i = 0; i < 2; i++)
                #pragma unroll
                for (int j = 0; j < 4; j++)
                    wmma::store_matrix_sync(&Cs[wm + i * 16][j * 16], c[i][j], 68,
                                            wmma::mem_row_major);
        }
        __syncthreads();

        const int bnp = bn + pass * 64;
        const float a_s0 = __ldg(att_src + bnp + lane * 2);
        const float a_s1 = __ldg(att_src + bnp + lane * 2 + 1);
        const float a_d0 = __ldg(att_dst + bnp + lane * 2);
        const float a_d1 = __ldg(att_dst + bnp + lane * 2 + 1);

        #pragma unroll
        for (int rr = 0; rr < 16; rr++) {
            int r = wid * 16 + rr;
            float2 v = *(const float2*)&Cs[r][lane * 2];
            ((__nv_bfloat162*)(hb + (size_t)(bm + r) * Nn + bnp))[lane] =
                __floats2bfloat162_rn(v.x, v.y);
            float s1 = v.x * a_s0 + v.y * a_s1;
            float s2 = v.x * a_d0 + v.y * a_d1;
            if (CH == 64) {
                #pragma unroll
                for (int o = 16; o > 0; o >>= 1) {
                    s1 += __shfl_xor_sync(0xffffffffu, s1, o);
                    s2 += __shfl_xor_sync(0xffffffffu, s2, o);
                }
                if (lane == 0) {
                    int head = bnp >> 6;
                    asrc[(bm + r) * HEADS + head] = s1;
                    adst[(bm + r) * HEADS + head] = s2;
                }
            } else {
                #pragma unroll
                for (int o = 8; o > 0; o >>= 1) {
                    s1 += __shfl_xor_sync(0xffffffffu, s1, o);
                    s2 += __shfl_xor_sync(0xffffffffu, s2, o);
                }
                if ((lane & 15) == 0) {
                    int head = (bnp >> 5) + (lane >> 4);
                    asrc[(bm + r) * HEADS + head] = s1;
                    adst[(bm + r) * HEADS + head] = s2;
                }
            }
        }
        __syncthreads();
    }
}

// ------------------- GAT aggregation (R9 geometry + FFMA2 inner loop) ----------
__device__ __forceinline__ void store_out(float* p, float v)  { *p = v; }
__device__ __forceinline__ void store_out(__half* p, float v) { *p = __float2half(v); }

template <int C, bool RELU, typename OT>
__global__ __launch_bounds__(256)
void aggregate_kernel(const __nv_bfloat16* __restrict__ h, const float* __restrict__ w,
                      const int* __restrict__ cnt, const int* __restrict__ csr,
                      const float* __restrict__ bias, OT* __restrict__ out) {
    constexpr int NQ = (C == 64) ? 4 : 8;
    const int node = blockIdx.x;
    const int wid = threadIdx.x >> 5;
    const int lane = threadIdx.x & 31;

    int head, cbase, q;
    if (C == 64) {
        q = wid >> 1;
        head = 4 * (wid & 1) + (lane >> 3);
        cbase = (lane & 7) * 8;
    } else {
        q = wid;
        head = lane >> 2;
        cbase = (lane & 3) * 8;
    }

    const int len = min(cnt[node], MAXDEG);
    const int chunk = (len + NQ - 1) / NQ;
    const int lo = node * MAXDEG + min(len, q * chunk);
    const int hi = node * MAXDEG + min(len, q * chunk + chunk);

    const unsigned rowBytes = (unsigned)(C * HEADS * 2);
    const unsigned laneOff  = (unsigned)(head * C + cbase) * 2u;
    const char* hbase = (const char*)h;

    float den = 0.f;
    unsigned long long acc2[4];
    #pragma unroll
    for (int v = 0; v < 4; v++) acc2[v] = 0ULL;

    #pragma unroll 2
    for (int j = lo; j < hi; j++) {
        int s = __ldg(&csr[j]);
        float wj = __ldg(&w[j * HEADS + head]);
        den += wj;
        unsigned long long wj2;
        asm("mov.b64 %0, {%1, %1};" : "=l"(wj2) : "f"(wj));
        unsigned off = (unsigned)s * rowBytes + laneOff;
        uint4 raw = __ldg((const uint4*)(hbase + off));
        unsigned raws[4] = {raw.x, raw.y, raw.z, raw.w};
        #pragma unroll
        for (int k = 0; k < 4; k++) {
            unsigned lo32 = raws[k] << 16;
            unsigned hi32 = raws[k] & 0xffff0000u;
            unsigned long long hv;
            asm("mov.b64 %0, {%1, %2};" : "=l"(hv) : "r"(lo32), "r"(hi32));
            asm("fma.rn.f32x2 %0, %1, %2, %0;" : "+l"(acc2[k]) : "l"(hv), "l"(wj2));
        }
    }

    __shared__ float sacc[NQ][HEADS][C];
    __shared__ float sden[NQ][HEADS];
    #pragma unroll
    for (int k = 0; k < 4; k++) {
        float a0, a1;
        asm("mov.b64 {%0, %1}, %2;" : "=f"(a0), "=f"(a1) : "l"(acc2[k]));
        sacc[q][head][cbase + 2 * k]     = a0;
        sacc[q][head][cbase + 2 * k + 1] = a1;
    }
    if (cbase == 0) sden[q][head] = den;
    __syncthreads();

    if (threadIdx.x < C) {
        int cc = threadIdx.x;
        float sum = 0.f;
        #pragma unroll
        for (int hh = 0; hh < HEADS; hh++) {
            float a = 0.f, d = 0.f;
            #pragma unroll
            for (int qq = 0; qq < NQ; qq++) {
                a += sacc[qq][hh][cc];
                d += sden[qq][hh];
            }
            sum += a / d;
        }
        sum = sum * (1.0f / HEADS) + bias[cc];
        if (RELU) sum = fmaxf(sum, 0.f);
        store_out(&out[(size_t)node * C + cc], sum);
    }
}

// ------------------- launch -------------------
extern "C" void kernel_launch(void* const* d_in, const int* in_sizes, int n_in,
                              void* d_out, int out_size) {
    const float* x        = (const float*)d_in[0];
    const int*   ei       = (const int*)  d_in[1];
    const float* W1       = (const float*)d_in[2];
    const float* att_src1 = (const float*)d_in[3];
    const float* att_dst1 = (const float*)d_in[4];
    const float* b1       = (const float*)d_in[5];
    const float* W2       = (const float*)d_in[6];
    const float* att_src2 = (const float*)d_in[7];
    const float* att_dst2 = (const float*)d_in[8];
    const float* b2       = (const float*)d_in[9];
    float* out = (float*)d_out;

    const int* src = ei;
    const int* dst = ei + E_EDGES;

    float *as1, *ad1, *as2, *ad2, *wbuf;
    __half *xh, *w1h, *w2h, *h1mh;
    __nv_bfloat16 *h1b, *h2b;
    int *cnt, *csr, *pos;
    cudaGetSymbolAddress((void**)&xh,   g_xh);
    cudaGetSymbolAddress((void**)&w1h,  g_w1h);
    cudaGetSymbolAddress((void**)&w2h,  g_w2h);
    cudaGetSymbolAddress((void**)&h1b,  g_h1b);
    cudaGetSymbolAddress((void**)&h1mh, g_h1mh);
    cudaGetSymbolAddress((void**)&h2b,  g_h2b);
    cudaGetSymbolAddress((void**)&as1,  g_as1);
    cudaGetSymbolAddress((void**)&ad1,  g_ad1);
    cudaGetSymbolAddress((void**)&as2,  g_as2);
    cudaGetSymbolAddress((void**)&ad2,  g_ad2);
    cudaGetSymbolAddress((void**)&wbuf, g_w);
    cudaGetSymbolAddress((void**)&cnt,  g_cnt);
    cudaGetSymbolAddress((void**)&csr,  g_csr);
    cudaGetSymbolAddress((void**)&pos,  g_pos);

    cudaStream_t st = 0;
    const int threads = 256;
    const int eblocks = (E_TOT + threads - 1) / threads;

    cudaMemsetAsync(cnt, 0, N_NODES * sizeof(int), st);
    scatter_kernel<<<eblocks, threads, 0, st>>>(src, dst, cnt, csr, pos);
    {
        int total = NX4 + NW14 + NW24;
        convert_kernel<<<(total + 255) / 256, 256, 0, st>>>(x, W1, W2, xh, w1h, w2h);
    }

    // Layer 1
    {
        dim3 grid(HEADS * HF / 128, (N_NODES + 127) / 128);
        gemm_fused_kernel<HF><<<grid, 256, 0, st>>>(xh, w1h, h1b, att_src1, att_dst1,
                                                    as1, ad1, HEADS * HF, IN_F);
        weight_kernel<<<eblocks, threads, 0, st>>>(src, dst, pos, as1, ad1, wbuf);
        aggregate_kernel<HF, true, __half><<<N_NODES, 256, 0, st>>>(h1b, wbuf, cnt, csr, b1, h1mh);
    }

    // Layer 2
    {
        dim3 grid(HEADS * OUTF / 128, (N_NODES + 127) / 128);
        gemm_fused_kernel<OUTF><<<grid, 256, 0, st>>>(h1mh, w2h, h2b, att_src2, att_dst2,
                                                      as2, ad2, HEADS * OUTF, HF);
        weight_kernel<<<eblocks, threads, 0, st>>>(src, dst, pos, as2, ad2, wbuf);
        aggregate_kernel<OUTF, false, float><<<N_NODES, 256, 0, st>>>(h2b, wbuf, cnt, csr, b2, out);
    }
}